// round 9
// baseline (speedup 1.0000x reference)
#include <cuda_runtime.h>
#include <cstdint>

// Chamfer distance via adaptive 1-D windowed NN search (exact).
// array1, array2 [B=4, N=4096, D=3] fp32.
// out = (100/32768) * sum over all 32768 per-point NN sq-dists (both dirs).
//
// min d2 = sq - 2*max_t,  t = q.c - 0.5|c|^2  (same dot-trick rounding that
// matched rel_err 1.3e-7 in R6-R8).
//
// Prep: bucket-sort each of the 8 (batch, array) combos by x (512 linear
// buckets over [-6,6]; |x|max ~4 for this input so clamps never trigger).
// Within-bucket order is nondeterministic but the search result is provably
// the exact NN (see below), so the value is order-independent.
//
// Search (the R8 fix): R8's one-shot bound from x-rank neighbors was weak
// (x-close != 3D-close: r ~0.3 -> ~1000-candidate windows -> no pruning).
// R9 expands ADAPTIVELY: scan seed window (+-32 ranks around the query's own
// rank), then loop: r_i = sqrt(max(sq-2M_i,0)) per lane, warp-union the
// needed x-interval, check coverage against sorted candidate x at the window
// edges (padded by one bucket width BW to absorb within-bucket disorder),
// extend 64 candidates toward the nearer uncovered side. M monotonically
// improves -> r converges to the true NN distance -> final window
// ~2*r_nn*density (~400 candidates, 10x pruning).
// Exactness: at termination the index window covers [qx-r_i, qx+r_i] for
// every lane; the true NN lies within r_i (since sq-2M_i >= true d2), so it
// is inside the window; max over any superset containing the global argmax
// equals t(NN) -> exact, deterministic.
//
// Mapping: warp = 8 consecutive sorted queries x 4 candidate-parity lanes.
// All window state is warp-uniform -> zero divergence; candidates broadcast
// from smem (4 distinct float4/iter, 8-way broadcast). ~7 issue slots per
// 32 pair-evals.

#define NBK 512
#define XLO (-6.0f)
#define XINVW (NBK / 12.0f)
#define BW (12.0f / NBK)
#define NPTS 4096
#define SBLK 256             // search blocks: 8 combos x 32
#define QPB 128              // queries per block (16 warps x 8)
#define CHUNK 64
#define INIT_HALF 32
#define NEG3 (-3.0e38f)

__device__ float4 g_sorted[8][NPTS];
__device__ float  g_partial[SBLK];
__device__ int    g_count;   // zero-init; self-resets each run

__device__ __forceinline__ int bucket_of(float x) {
    int bk = (int)((x - XLO) * XINVW);
    bk = bk < 0 ? 0 : bk;
    return bk > NBK - 1 ? NBK - 1 : bk;
}

// ---------------- kernel 1: bucket-sort the 8 arrays by x ----------------
__global__ __launch_bounds__(512) void chamfer_prep(
    const float* __restrict__ a1, const float* __restrict__ a2)
{
    __shared__ int sh[NBK];
    __shared__ int soff[NBK];

    const int c = blockIdx.x;            // combo 0..7 = b*2 + arr
    const int b = c >> 1;
    const float* src = ((c & 1) ? a2 : a1) + (size_t)b * NPTS * 3;
    const int t = threadIdx.x;           // 512 == NBK

    sh[t] = 0;
    __syncthreads();

    float px[8], py[8], pz[8];
    int   bk[8];
#pragma unroll
    for (int k = 0; k < 8; k++) {
        const int i = t + k * 512;
        px[k] = src[i * 3 + 0];
        py[k] = src[i * 3 + 1];
        pz[k] = src[i * 3 + 2];
        bk[k] = bucket_of(px[k]);
        atomicAdd(&sh[bk[k]], 1);
    }
    __syncthreads();

    for (int off = 1; off < NBK; off <<= 1) {     // inclusive scan
        const int v = (t >= off) ? sh[t - off] : 0;
        __syncthreads();
        sh[t] += v;
        __syncthreads();
    }

    soff[t] = (t == 0) ? 0 : sh[t - 1];
    __syncthreads();

#pragma unroll
    for (int k = 0; k < 8; k++) {
        const int r = atomicAdd(&soff[bk[k]], 1);
        g_sorted[c][r] = make_float4(px[k], py[k], pz[k],
            -0.5f * (px[k] * px[k] + py[k] * py[k] + pz[k] * pz[k]));
    }
}

// ---------------- kernel 2: adaptive windowed search ----------------
__global__ __launch_bounds__(512) void chamfer_search(float* __restrict__ out)
{
    extern __shared__ float4 scand[];        // 4096 * 16 B = 64 KB dynamic
    __shared__ float s_red[16];
    __shared__ int   s_last;

    const int t   = threadIdx.x;
    const int wid = t >> 5, ln = t & 31;
    const int c   = blockIdx.x >> 5;         // query combo 0..7
    const int cc  = c ^ 1;                   // candidate combo

    for (int i = t; i < NPTS; i += 512) scand[i] = g_sorted[cc][i];
    __syncthreads();

    const int ql   = ln >> 2;                // query lane 0..7
    const int coff = ln & 3;                 // candidate parity 0..3
    const int qbase = (blockIdx.x & 31) * QPB + wid * 8;
    const int q = qbase + ql;                // sorted query rank (0..4095)

    const float4 Q = g_sorted[c][q];
    const float qx = Q.x, qy = Q.y, qz = Q.z;
    const float sq = -2.0f * Q.w;            // |q|^2

    // warp-uniform seed window around the group's mid rank
    const int qm = qbase + 4;
    int curL = qm - INIT_HALF; curL = curL < 0 ? 0 : curL;
    int curR = qm + INIT_HALF; curR = curR > NPTS ? NPTS : curR;

    float M = NEG3;
    for (int i = curL + coff; i < curR; i += 4) {
        const float4 C = scand[i];
        const float tt = fmaf(qx, C.x, fmaf(qy, C.y, fmaf(qz, C.z, C.w)));
        M = fmaxf(M, tt);
    }

    while (true) {
        // per-lane radius, warp-union of needed x-interval
        const float bd = fmaxf(fmaf(-2.0f, M, sq), 0.0f);
        const float r  = sqrtf(bd);
        float lox = qx - r, hix = qx + r;
#pragma unroll
        for (int o = 16; o; o >>= 1) {
            lox = fminf(lox, __shfl_xor_sync(0xffffffffu, lox, o));
            hix = fmaxf(hix, __shfl_xor_sync(0xffffffffu, hix, o));
        }

        // coverage check at window edges (BW pad for within-bucket disorder)
        float xL = 0.0f, xR = 0.0f;
        const bool hasL = (curL > 0), hasR = (curR < NPTS);
        if (hasL) xL = scand[curL - 1].x;    // uniform -> broadcast
        if (hasR) xR = scand[curR].x;
        const bool doneL = !hasL || (xL < lox - BW);
        const bool doneR = !hasR || (xR > hix + BW);
        if (doneL && doneR) break;

        // extend toward the nearer uncovered side
        const float gapL = doneL ? 3.0e38f : lox - xL;
        const float gapR = doneR ? 3.0e38f : xR - hix;
        int a, b;
        if (gapL <= gapR) {
            a = curL - CHUNK; a = a < 0 ? 0 : a;
            b = curL; curL = a;
        } else {
            a = curR;
            b = curR + CHUNK; b = b > NPTS ? NPTS : b;
            curR = b;
        }
        for (int i = a + coff; i < b; i += 4) {
            const float4 C = scand[i];
            const float tt = fmaf(qx, C.x, fmaf(qy, C.y, fmaf(qz, C.z, C.w)));
            M = fmaxf(M, tt);
        }
    }

    // combine the 4 candidate-parity lanes of each query (max -> min d2)
    float Mq = M;
#pragma unroll
    for (int o = 1; o <= 2; o <<= 1)
        Mq = fmaxf(Mq, __shfl_xor_sync(0xffffffffu, Mq, o));
    const float d2 = fmaf(-2.0f, Mq, sq);

    // sum the 8 query d2 values of this warp (coff==0 lanes contribute)
    float v = (coff == 0) ? d2 : 0.0f;
#pragma unroll
    for (int o = 16; o; o >>= 1) v += __shfl_xor_sync(0xffffffffu, v, o);
    if (ln == 0) s_red[wid] = v;
    __syncthreads();

    if (t == 0) {
        float rsum = 0.0f;
#pragma unroll
        for (int g = 0; g < 16; g++) rsum += s_red[g];
        g_partial[blockIdx.x] = rsum;
        __threadfence();
        const int old = atomicAdd(&g_count, 1);
        s_last = (old == SBLK - 1);
    }
    __syncthreads();

    // last block: warp 0 sums the 256 partials in fixed order (deterministic)
    if (s_last && wid == 0) {
        __threadfence();
        float s = 0.0f;
#pragma unroll
        for (int k = 0; k < SBLK / 32; k++) s += g_partial[ln + k * 32];
#pragma unroll
        for (int o = 16; o; o >>= 1) s += __shfl_down_sync(0xffffffffu, s, o);
        if (ln == 0) {
            out[0] = s * (100.0f / 32768.0f);
            g_count = 0;      // reset for next graph replay
        }
    }
}

extern "C" void kernel_launch(void* const* d_in, const int* in_sizes, int n_in,
                              void* d_out, int out_size)
{
    const float* a1 = (const float*)d_in[0];
    const float* a2 = (const float*)d_in[1];
    float* out = (float*)d_out;

    cudaFuncSetAttribute(chamfer_search,
                         cudaFuncAttributeMaxDynamicSharedMemorySize,
                         NPTS * sizeof(float4));

    chamfer_prep<<<8, 512>>>(a1, a2);
    chamfer_search<<<SBLK, 512, NPTS * sizeof(float4)>>>(out);
}